// round 1
// baseline (speedup 1.0000x reference)
#include <cuda_runtime.h>

#define T_SEQ 2048
#define NHEADS 16
#define NEMB 1024
#define HD 64
#define BATCH 4

// Scratch (no allocation allowed): qkv projection output and attention output.
__device__ float g_qkv[(size_t)BATCH * T_SEQ * 3 * NEMB];   // [B*T, 3072]
__device__ float g_attn[(size_t)BATCH * T_SEQ * NEMB];      // [B*T, 1024]

// ---------------------------------------------------------------------------
// Generic fp32 GEMM: C[M,N] = A[M,K] @ B[K,N] (+ bias[N] if non-null)
// 64x64 block tile, 256 threads, 4x4 register microtile, K-tile 16,
// reg->smem double buffering (one __syncthreads per K-tile).
// Requires M%64==0, N%64==0, K%16==0 (true for all three calls).
// ---------------------------------------------------------------------------
__global__ __launch_bounds__(256) void gemm64(const float* __restrict__ A,
                                              const float* __restrict__ B,
                                              const float* __restrict__ bias,
                                              float* __restrict__ C,
                                              int M, int N, int K) {
    __shared__ float As[2][16][68];   // [buf][k][m], pitch 68 (aligned, low-conflict)
    __shared__ float Bs[2][16][64];   // [buf][k][n]

    const int tid = threadIdx.x;
    const int tx = tid & 15;          // n-microtile
    const int ty = tid >> 4;          // m-microtile
    const int m0 = blockIdx.y * 64;
    const int n0 = blockIdx.x * 64;

    const float* Ab = A + (size_t)m0 * K;
    const float* Bb = B + n0;

    float acc[4][4];
#pragma unroll
    for (int i = 0; i < 4; i++)
#pragma unroll
        for (int j = 0; j < 4; j++) acc[i][j] = 0.f;

    float ra[4], rb[4];
    // preload tile 0
#pragma unroll
    for (int i = 0; i < 4; i++) {
        int id = tid + i * 256;
        ra[i] = Ab[(id >> 4) * K + (id & 15)];
        rb[i] = Bb[(id >> 6) * N + (id & 63)];
    }
#pragma unroll
    for (int i = 0; i < 4; i++) {
        int id = tid + i * 256;
        As[0][id & 15][id >> 4] = ra[i];
        Bs[0][id >> 6][id & 63] = rb[i];
    }
    __syncthreads();

    const int NK = K >> 4;
    for (int kt = 0; kt < NK; kt++) {
        const int cur = kt & 1;
        if (kt + 1 < NK) {
            const int k0 = (kt + 1) << 4;
#pragma unroll
            for (int i = 0; i < 4; i++) {
                int id = tid + i * 256;
                ra[i] = Ab[(id >> 4) * K + k0 + (id & 15)];
                rb[i] = Bb[(k0 + (id >> 6)) * N + (id & 63)];
            }
        }
#pragma unroll
        for (int k = 0; k < 16; k++) {
            float4 a4 = *(const float4*)&As[cur][k][ty * 4];
            float4 b4 = *(const float4*)&Bs[cur][k][tx * 4];
            float av[4] = {a4.x, a4.y, a4.z, a4.w};
            float bv[4] = {b4.x, b4.y, b4.z, b4.w};
#pragma unroll
            for (int i = 0; i < 4; i++)
#pragma unroll
                for (int j = 0; j < 4; j++) acc[i][j] += av[i] * bv[j];
        }
        if (kt + 1 < NK) {
            const int nb = cur ^ 1;
#pragma unroll
            for (int i = 0; i < 4; i++) {
                int id = tid + i * 256;
                As[nb][id & 15][id >> 4] = ra[i];
                Bs[nb][id >> 6][id & 63] = rb[i];
            }
        }
        __syncthreads();
    }

    float bv[4] = {0.f, 0.f, 0.f, 0.f};
    if (bias) {
#pragma unroll
        for (int j = 0; j < 4; j++) bv[j] = bias[n0 + tx * 4 + j];
    }
#pragma unroll
    for (int i = 0; i < 4; i++) {
        float4 o = make_float4(acc[i][0] + bv[0], acc[i][1] + bv[1],
                               acc[i][2] + bv[2], acc[i][3] + bv[3]);
        *(float4*)&C[(size_t)(m0 + ty * 4 + i) * N + n0 + tx * 4] = o;
    }
}

// ---------------------------------------------------------------------------
// Causal flash attention, fp32. One block per (b, h, 64-query tile).
// 256 threads = 16x16, each thread owns a 4x4 microtile (rows=ty*4.., cols=tx*4..).
// Q and K staged transposed [d][row] (pitch 68) -> conflict-free S microkernel.
// P reuses the K buffer; V natural [key][d]. Softmax state in registers,
// reduced with shfl across the 16-lane row-group.
// ---------------------------------------------------------------------------
#define PITCH 68
#define TILE_F (64 * PITCH)

__global__ __launch_bounds__(256) void attn64(const float* __restrict__ qkv,
                                              float* __restrict__ out) {
    extern __shared__ float sm[];
    float* Qt = sm;                 // [d][row]  (d*PITCH + r)
    float* Kt = sm + TILE_F;        // [d][key]; later P[key][row]
    float* Vs = sm + 2 * TILE_F;    // [key][d]  (key*PITCH + d)

    const int tid = threadIdx.x;
    const int tx = tid & 15;
    const int ty = tid >> 4;
    const int qt = blockIdx.x;                 // query tile 0..31
    const int b = blockIdx.y >> 4;
    const int h = blockIdx.y & 15;

    const float* base = qkv + (size_t)b * T_SEQ * (3 * NEMB) + h * HD;

    // Load Q tile (transposed, pre-scaled by 1/sqrt(D) = 0.125)
#pragma unroll
    for (int i = 0; i < 4; i++) {
        int id = tid + i * 256;
        int r = id >> 4, d4 = id & 15;
        float4 v = *(const float4*)(base + (size_t)(qt * 64 + r) * (3 * NEMB) + d4 * 4);
        Qt[(d4 * 4 + 0) * PITCH + r] = v.x * 0.125f;
        Qt[(d4 * 4 + 1) * PITCH + r] = v.y * 0.125f;
        Qt[(d4 * 4 + 2) * PITCH + r] = v.z * 0.125f;
        Qt[(d4 * 4 + 3) * PITCH + r] = v.w * 0.125f;
    }

    float m_i[4], l_i[4], O[4][4];
#pragma unroll
    for (int i = 0; i < 4; i++) {
        m_i[i] = -1e30f;
        l_i[i] = 0.f;
#pragma unroll
        for (int j = 0; j < 4; j++) O[i][j] = 0.f;
    }

    for (int kt = 0; kt <= qt; kt++) {
        __syncthreads();   // previous PV readers done before overwriting Kt/Vs
        // Load K tile (transposed) and V tile (natural)
#pragma unroll
        for (int i = 0; i < 4; i++) {
            int id = tid + i * 256;
            int r = id >> 4, d4 = id & 15;
            const float* kp = base + NEMB + (size_t)(kt * 64 + r) * (3 * NEMB) + d4 * 4;
            float4 kv = *(const float4*)kp;
            float4 vv = *(const float4*)(kp + NEMB);
            Kt[(d4 * 4 + 0) * PITCH + r] = kv.x;
            Kt[(d4 * 4 + 1) * PITCH + r] = kv.y;
            Kt[(d4 * 4 + 2) * PITCH + r] = kv.z;
            Kt[(d4 * 4 + 3) * PITCH + r] = kv.w;
            *(float4*)&Vs[r * PITCH + d4 * 4] = vv;
        }
        __syncthreads();

        // S = Q K^T  (64x64x64)
        float s[4][4];
#pragma unroll
        for (int i = 0; i < 4; i++)
#pragma unroll
            for (int j = 0; j < 4; j++) s[i][j] = 0.f;

#pragma unroll 16
        for (int k = 0; k < 64; k++) {
            float a0 = Qt[k * PITCH + ty * 4 + 0];
            float a1 = Qt[k * PITCH + ty * 4 + 1];
            float a2 = Qt[k * PITCH + ty * 4 + 2];
            float a3 = Qt[k * PITCH + ty * 4 + 3];
            float4 b4 = *(const float4*)&Kt[k * PITCH + tx * 4];
            s[0][0] += a0 * b4.x; s[0][1] += a0 * b4.y; s[0][2] += a0 * b4.z; s[0][3] += a0 * b4.w;
            s[1][0] += a1 * b4.x; s[1][1] += a1 * b4.y; s[1][2] += a1 * b4.z; s[1][3] += a1 * b4.w;
            s[2][0] += a2 * b4.x; s[2][1] += a2 * b4.y; s[2][2] += a2 * b4.z; s[2][3] += a2 * b4.w;
            s[3][0] += a3 * b4.x; s[3][1] += a3 * b4.y; s[3][2] += a3 * b4.z; s[3][3] += a3 * b4.w;
        }

        if (kt == qt) {     // causal mask on the diagonal tile only
#pragma unroll
            for (int i = 0; i < 4; i++)
#pragma unroll
                for (int j = 0; j < 4; j++)
                    if (tx * 4 + j > ty * 4 + i) s[i][j] = -1e30f;
        }

        // Online softmax update (per-row; 16-lane row-group reductions)
#pragma unroll
        for (int i = 0; i < 4; i++) {
            float pm = fmaxf(fmaxf(s[i][0], s[i][1]), fmaxf(s[i][2], s[i][3]));
            pm = fmaxf(pm, __shfl_xor_sync(0xffffffffu, pm, 1));
            pm = fmaxf(pm, __shfl_xor_sync(0xffffffffu, pm, 2));
            pm = fmaxf(pm, __shfl_xor_sync(0xffffffffu, pm, 4));
            pm = fmaxf(pm, __shfl_xor_sync(0xffffffffu, pm, 8));
            float mn = fmaxf(m_i[i], pm);
            float al = __expf(m_i[i] - mn);
            m_i[i] = mn;
            float rs = 0.f;
#pragma unroll
            for (int j = 0; j < 4; j++) {
                s[i][j] = __expf(s[i][j] - mn);
                rs += s[i][j];
            }
            rs += __shfl_xor_sync(0xffffffffu, rs, 1);
            rs += __shfl_xor_sync(0xffffffffu, rs, 2);
            rs += __shfl_xor_sync(0xffffffffu, rs, 4);
            rs += __shfl_xor_sync(0xffffffffu, rs, 8);
            l_i[i] = l_i[i] * al + rs;
#pragma unroll
            for (int j = 0; j < 4; j++) O[i][j] *= al;
        }

        __syncthreads();    // everyone done reading Kt before it becomes P
        // P[key][row] into Kt buffer
#pragma unroll
        for (int i = 0; i < 4; i++)
#pragma unroll
            for (int j = 0; j < 4; j++)
                Kt[(tx * 4 + j) * PITCH + ty * 4 + i] = s[i][j];
        __syncthreads();

        // O += P V  (64x64x64)
#pragma unroll 16
        for (int k = 0; k < 64; k++) {
            float a0 = Kt[k * PITCH + ty * 4 + 0];
            float a1 = Kt[k * PITCH + ty * 4 + 1];
            float a2 = Kt[k * PITCH + ty * 4 + 2];
            float a3 = Kt[k * PITCH + ty * 4 + 3];
            float4 b4 = *(const float4*)&Vs[k * PITCH + tx * 4];
            O[0][0] += a0 * b4.x; O[0][1] += a0 * b4.y; O[0][2] += a0 * b4.z; O[0][3] += a0 * b4.w;
            O[1][0] += a1 * b4.x; O[1][1] += a1 * b4.y; O[1][2] += a1 * b4.z; O[1][3] += a1 * b4.w;
            O[2][0] += a2 * b4.x; O[2][1] += a2 * b4.y; O[2][2] += a2 * b4.z; O[2][3] += a2 * b4.w;
            O[3][0] += a3 * b4.x; O[3][1] += a3 * b4.y; O[3][2] += a3 * b4.z; O[3][3] += a3 * b4.w;
        }
    }

    // Epilogue: normalize and store to [B*T, C] with head-major columns
#pragma unroll
    for (int i = 0; i < 4; i++) {
        float inv = 1.0f / l_i[i];
        float4 o = make_float4(O[i][0] * inv, O[i][1] * inv, O[i][2] * inv, O[i][3] * inv);
        size_t row = (size_t)b * T_SEQ + qt * 64 + ty * 4 + i;
        *(float4*)&out[row * NEMB + h * HD + tx * 4] = o;
    }
}

// ---------------------------------------------------------------------------
// kernel_launch: qkv GEMM -> flash attention -> out GEMM (+bias)
// ---------------------------------------------------------------------------
extern "C" void kernel_launch(void* const* d_in, const int* in_sizes, int n_in,
                              void* d_out, int out_size) {
    const float* x     = (const float*)d_in[0];   // [B,T,C]
    const float* w_qkv = (const float*)d_in[1];   // [C,3C]
    const float* w_out = (const float*)d_in[2];   // [C,C]
    const float* b_out = (const float*)d_in[3];   // [C]
    float* out = (float*)d_out;

    float* qkv = nullptr;
    float* attn = nullptr;
    cudaGetSymbolAddress((void**)&qkv, g_qkv);
    cudaGetSymbolAddress((void**)&attn, g_attn);

    const int ATTN_SMEM = 3 * TILE_F * (int)sizeof(float);   // 52224 B
    cudaFuncSetAttribute(attn64, cudaFuncAttributeMaxDynamicSharedMemorySize, ATTN_SMEM);

    const int M = BATCH * T_SEQ;    // 8192
    dim3 blk(256);

    // 1) qkv = x @ w_qkv            [8192, 3072]
    gemm64<<<dim3(3 * NEMB / 64, M / 64), blk>>>(x, w_qkv, nullptr, qkv, M, 3 * NEMB, NEMB);

    // 2) causal flash attention -> attn [8192, 1024]
    attn64<<<dim3(T_SEQ / 64, BATCH * NHEADS), blk, ATTN_SMEM>>>(qkv, attn);

    // 3) out = attn @ w_out + b_out [8192, 1024]
    gemm64<<<dim3(NEMB / 64, M / 64), blk>>>(attn, w_out, b_out, out, M, NEMB, NEMB);
}

// round 3
// speedup vs baseline: 1.8037x; 1.8037x over previous
#include <cuda_runtime.h>
#include <cstdint>

#define T_SEQ 2048
#define NHEADS 16
#define NEMB 1024
#define HD 64
#define BATCH 4

// ---------------------------------------------------------------------------
// Scratch (no allocation allowed anywhere)
// ---------------------------------------------------------------------------
__device__ float g_qkv[(size_t)BATCH * T_SEQ * 3 * NEMB];   // [8192, 3072]
__device__ float g_attn[(size_t)BATCH * T_SEQ * NEMB];      // [8192, 1024]

// ---------------------------------------------------------------------------
// PTX helpers (baseline PTX only — sm_103 non-'a' target!)
// ---------------------------------------------------------------------------
__device__ __forceinline__ uint32_t smem_to_u32(const void* p) {
    uint32_t a;
    asm("{ .reg .u64 t; cvta.to.shared.u64 t, %1; cvt.u32.u64 %0, t; }" : "=r"(a) : "l"(p));
    return a;
}
__device__ __forceinline__ uint32_t f2tf32(float f) {
    uint32_t u;
    asm("cvt.rna.tf32.f32 %0, %1;" : "=r"(u) : "f"(f));
    return u;
}
__device__ __forceinline__ void mma_tf32(float* d, const uint32_t* a, const uint32_t* b) {
    asm volatile(
        "mma.sync.aligned.m16n8k8.row.col.f32.tf32.tf32.f32 "
        "{%0,%1,%2,%3}, {%4,%5,%6,%7}, {%8,%9}, {%0,%1,%2,%3};"
        : "+f"(d[0]), "+f"(d[1]), "+f"(d[2]), "+f"(d[3])
        : "r"(a[0]), "r"(a[1]), "r"(a[2]), "r"(a[3]), "r"(b[0]), "r"(b[1]));
}
#define CP_ASYNC16(dst, src) \
    asm volatile("cp.async.cg.shared.global [%0], [%1], 16;" :: "r"(dst), "l"(src))
#define CP_COMMIT()  asm volatile("cp.async.commit_group;" ::: "memory")
#define CP_WAIT1()   asm volatile("cp.async.wait_group 1;" ::: "memory")
#define CP_WAIT0()   asm volatile("cp.async.wait_group 0;" ::: "memory")

// ---------------------------------------------------------------------------
// tf32 mma.sync GEMM:  C[M,N] = A[M,K] @ B[K,N]  (+bias)
// CTA 128x128, K-tile 32, 8 warps (2M x 4N, warp tile 64x32), cp.async
// 2-stage pipeline. Smem pitches chosen for conflict-free LDS.32 fragments:
//   A [m][k] pitch 36 floats (bank = 4m+k mod 32 -> 32 distinct)
//   B [k][n] pitch 136 floats (bank = 8k+n mod 32 -> 32 distinct)
// ---------------------------------------------------------------------------
#define A_STAGE 4608            // 128*36 floats
#define B_STAGE 4352            // 32*136 floats
#define GE_SMEM_FLOATS (2 * (A_STAGE + B_STAGE))
#define GE_SMEM_BYTES (GE_SMEM_FLOATS * 4)   // 71680

__global__ __launch_bounds__(256) void mma_gemm(const float* __restrict__ A,
                                                const float* __restrict__ B,
                                                const float* __restrict__ bias,
                                                float* __restrict__ C,
                                                int M, int N, int K) {
    extern __shared__ float sm[];
    const uint32_t sbase = smem_to_u32(sm);
    const int tid = threadIdx.x;
    const int wid = tid >> 5, lane = tid & 31;
    const int wm = wid & 1, wn = wid >> 1;          // warp grid 2(M) x 4(N)
    const int lr = lane >> 2, kc = lane & 3;        // fragment row / k-col
    const int m0 = blockIdx.y * 128, n0 = blockIdx.x * 128;

    // tile loader: A rows m0..m0+127, k window c*32..+32; B rows c*32..+32, cols n0..+127
    auto load_tile = [&](int c, int buf) {
        const uint32_t asb = sbase + (buf ? A_STAGE : 0) * 4;
        const uint32_t bsb = sbase + (2 * A_STAGE + (buf ? B_STAGE : 0)) * 4;
        const float* Ac = A + (size_t)m0 * K + c * 32;
        const float* Bc = B + (size_t)(c * 32) * N + n0;
#pragma unroll
        for (int i = 0; i < 4; i++) {
            int id = tid + i * 256;
            int am = id >> 3, ak4 = id & 7;
            CP_ASYNC16(asb + (uint32_t)(am * 36 + ak4 * 4) * 4,
                       Ac + (size_t)am * K + ak4 * 4);
            int br = id >> 5, bn4 = id & 31;
            CP_ASYNC16(bsb + (uint32_t)(br * 136 + bn4 * 4) * 4,
                       Bc + (size_t)br * N + bn4 * 4);
        }
        CP_COMMIT();
    };

    float acc[4][4][4];
#pragma unroll
    for (int i = 0; i < 4; i++)
#pragma unroll
        for (int j = 0; j < 4; j++)
#pragma unroll
            for (int r = 0; r < 4; r++) acc[i][j][r] = 0.f;

    const int NT = K >> 5;
    load_tile(0, 0);

    for (int c = 0; c < NT; c++) {
        const int buf = c & 1;
        if (c + 1 < NT) { load_tile(c + 1, buf ^ 1); CP_WAIT1(); }
        else            { CP_WAIT0(); }
        __syncthreads();

        const float* As = sm + (buf ? A_STAGE : 0);
        const float* Bs = sm + 2 * A_STAGE + (buf ? B_STAGE : 0);
        const int mbase = wm * 64;
        const int nbase = wn * 32;

#pragma unroll
        for (int kk = 0; kk < 4; kk++) {
            uint32_t af[4][4], bf[4][2];
#pragma unroll
            for (int mt = 0; mt < 4; mt++) {
                const float* ap = As + (mbase + mt * 16 + lr) * 36 + kk * 8 + kc;
                af[mt][0] = f2tf32(ap[0]);
                af[mt][1] = f2tf32(ap[8 * 36]);
                af[mt][2] = f2tf32(ap[4]);
                af[mt][3] = f2tf32(ap[8 * 36 + 4]);
            }
#pragma unroll
            for (int nt = 0; nt < 4; nt++) {
                const float* bp = Bs + (kk * 8 + kc) * 136 + nbase + nt * 8 + lr;
                bf[nt][0] = f2tf32(bp[0]);
                bf[nt][1] = f2tf32(bp[4 * 136]);
            }
#pragma unroll
            for (int mt = 0; mt < 4; mt++)
#pragma unroll
                for (int nt = 0; nt < 4; nt++)
                    mma_tf32(acc[mt][nt], af[mt], bf[nt]);
        }
        __syncthreads();   // protect buf from the overwrite issued next iter
    }

    // Epilogue: c0,c1 at (row, 2*kc), (row, 2*kc+1); c2,c3 at row+8.
#pragma unroll
    for (int mt = 0; mt < 4; mt++) {
        const int row = m0 + wm * 64 + mt * 16 + lr;
#pragma unroll
        for (int nt = 0; nt < 4; nt++) {
            const int col = n0 + wn * 32 + nt * 8 + kc * 2;
            float b0 = 0.f, b1 = 0.f;
            if (bias) { b0 = bias[col]; b1 = bias[col + 1]; }
            float2 v0 = make_float2(acc[mt][nt][0] + b0, acc[mt][nt][1] + b1);
            float2 v1 = make_float2(acc[mt][nt][2] + b0, acc[mt][nt][3] + b1);
            *(float2*)&C[(size_t)row * N + col] = v0;
            *(float2*)&C[(size_t)(row + 8) * N + col] = v1;
        }
    }
}

// ---------------------------------------------------------------------------
// Causal flash attention, fp32 (unchanged — next round's target).
// ---------------------------------------------------------------------------
#define PITCH 68
#define TILE_F (64 * PITCH)

__global__ __launch_bounds__(256) void attn64(const float* __restrict__ qkv,
                                              float* __restrict__ out) {
    extern __shared__ float sm[];
    float* Qt = sm;
    float* Kt = sm + TILE_F;
    float* Vs = sm + 2 * TILE_F;

    const int tid = threadIdx.x;
    const int tx = tid & 15;
    const int ty = tid >> 4;
    const int qt = blockIdx.x;
    const int b = blockIdx.y >> 4;
    const int h = blockIdx.y & 15;

    const float* base = qkv + (size_t)b * T_SEQ * (3 * NEMB) + h * HD;

#pragma unroll
    for (int i = 0; i < 4; i++) {
        int id = tid + i * 256;
        int r = id >> 4, d4 = id & 15;
        float4 v = *(const float4*)(base + (size_t)(qt * 64 + r) * (3 * NEMB) + d4 * 4);
        Qt[(d4 * 4 + 0) * PITCH + r] = v.x * 0.125f;
        Qt[(d4 * 4 + 1) * PITCH + r] = v.y * 0.125f;
        Qt[(d4 * 4 + 2) * PITCH + r] = v.z * 0.125f;
        Qt[(d4 * 4 + 3) * PITCH + r] = v.w * 0.125f;
    }

    float m_i[4], l_i[4], O[4][4];
#pragma unroll
    for (int i = 0; i < 4; i++) {
        m_i[i] = -1e30f;
        l_i[i] = 0.f;
#pragma unroll
        for (int j = 0; j < 4; j++) O[i][j] = 0.f;
    }

    for (int kt = 0; kt <= qt; kt++) {
        __syncthreads();
#pragma unroll
        for (int i = 0; i < 4; i++) {
            int id = tid + i * 256;
            int r = id >> 4, d4 = id & 15;
            const float* kp = base + NEMB + (size_t)(kt * 64 + r) * (3 * NEMB) + d4 * 4;
            float4 kv = *(const float4*)kp;
            float4 vv = *(const float4*)(kp + NEMB);
            Kt[(d4 * 4 + 0) * PITCH + r] = kv.x;
            Kt[(d4 * 4 + 1) * PITCH + r] = kv.y;
            Kt[(d4 * 4 + 2) * PITCH + r] = kv.z;
            Kt[(d4 * 4 + 3) * PITCH + r] = kv.w;
            *(float4*)&Vs[r * PITCH + d4 * 4] = vv;
        }
        __syncthreads();

        float s[4][4];
#pragma unroll
        for (int i = 0; i < 4; i++)
#pragma unroll
            for (int j = 0; j < 4; j++) s[i][j] = 0.f;

#pragma unroll 16
        for (int k = 0; k < 64; k++) {
            float a0 = Qt[k * PITCH + ty * 4 + 0];
            float a1 = Qt[k * PITCH + ty * 4 + 1];
            float a2 = Qt[k * PITCH + ty * 4 + 2];
            float a3 = Qt[k * PITCH + ty * 4 + 3];
            float4 b4 = *(const float4*)&Kt[k * PITCH + tx * 4];
            s[0][0] += a0 * b4.x; s[0][1] += a0 * b4.y; s[0][2] += a0 * b4.z; s[0][3] += a0 * b4.w;
            s[1][0] += a1 * b4.x; s[1][1] += a1 * b4.y; s[1][2] += a1 * b4.z; s[1][3] += a1 * b4.w;
            s[2][0] += a2 * b4.x; s[2][1] += a2 * b4.y; s[2][2] += a2 * b4.z; s[2][3] += a2 * b4.w;
            s[3][0] += a3 * b4.x; s[3][1] += a3 * b4.y; s[3][2] += a3 * b4.z; s[3][3] += a3 * b4.w;
        }

        if (kt == qt) {
#pragma unroll
            for (int i = 0; i < 4; i++)
#pragma unroll
                for (int j = 0; j < 4; j++)
                    if (tx * 4 + j > ty * 4 + i) s[i][j] = -1e30f;
        }

#pragma unroll
        for (int i = 0; i < 4; i++) {
            float pm = fmaxf(fmaxf(s[i][0], s[i][1]), fmaxf(s[i][2], s[i][3]));
            pm = fmaxf(pm, __shfl_xor_sync(0xffffffffu, pm, 1));
            pm = fmaxf(pm, __shfl_xor_sync(0xffffffffu, pm, 2));
            pm = fmaxf(pm, __shfl_xor_sync(0xffffffffu, pm, 4));
            pm = fmaxf(pm, __shfl_xor_sync(0xffffffffu, pm, 8));
            float mn = fmaxf(m_i[i], pm);
            float al = __expf(m_i[i] - mn);
            m_i[i] = mn;
            float rs = 0.f;
#pragma unroll
            for (int j = 0; j < 4; j++) {
                s[i][j] = __expf(s[i][j] - mn);
                rs += s[i][j];
            }
            rs += __shfl_xor_sync(0xffffffffu, rs, 1);
            rs += __shfl_xor_sync(0xffffffffu, rs, 2);
            rs += __shfl_xor_sync(0xffffffffu, rs, 4);
            rs += __shfl_xor_sync(0xffffffffu, rs, 8);
            l_i[i] = l_i[i] * al + rs;
#pragma unroll
            for (int j = 0; j < 4; j++) O[i][j] *= al;
        }

        __syncthreads();
#pragma unroll
        for (int i = 0; i < 4; i++)
#pragma unroll
            for (int j = 0; j < 4; j++)
                Kt[(tx * 4 + j) * PITCH + ty * 4 + i] = s[i][j];
        __syncthreads();

#pragma unroll 16
        for (int k = 0; k < 64; k++) {
            float a0 = Kt[k * PITCH + ty * 4 + 0];
            float a1 = Kt[k * PITCH + ty * 4 + 1];
            float a2 = Kt[k * PITCH + ty * 4 + 2];
            float a3 = Kt[k * PITCH + ty * 4 + 3];
            float4 b4 = *(const float4*)&Vs[k * PITCH + tx * 4];
            O[0][0] += a0 * b4.x; O[0][1] += a0 * b4.y; O[0][2] += a0 * b4.z; O[0][3] += a0 * b4.w;
            O[1][0] += a1 * b4.x; O[1][1] += a1 * b4.y; O[1][2] += a1 * b4.z; O[1][3] += a1 * b4.w;
            O[2][0] += a2 * b4.x; O[2][1] += a2 * b4.y; O[2][2] += a2 * b4.z; O[2][3] += a2 * b4.w;
            O[3][0] += a3 * b4.x; O[3][1] += a3 * b4.y; O[3][2] += a3 * b4.z; O[3][3] += a3 * b4.w;
        }
    }

#pragma unroll
    for (int i = 0; i < 4; i++) {
        float inv = 1.0f / l_i[i];
        float4 o = make_float4(O[i][0] * inv, O[i][1] * inv, O[i][2] * inv, O[i][3] * inv);
        size_t row = (size_t)b * T_SEQ + qt * 64 + ty * 4 + i;
        *(float4*)&out[row * NEMB + h * HD + tx * 4] = o;
    }
}

// ---------------------------------------------------------------------------
// kernel_launch: qkv GEMM -> flash attention -> out GEMM (+bias)
// ---------------------------------------------------------------------------
extern "C" void kernel_launch(void* const* d_in, const int* in_sizes, int n_in,
                              void* d_out, int out_size) {
    const float* x     = (const float*)d_in[0];   // [B,T,C]
    const float* w_qkv = (const float*)d_in[1];   // [C,3C]  (native [K,N] = B col-major!)
    const float* w_out = (const float*)d_in[2];   // [C,C]
    const float* b_out = (const float*)d_in[3];   // [C]
    float* out = (float*)d_out;

    float *qkv, *attn;
    cudaGetSymbolAddress((void**)&qkv, g_qkv);
    cudaGetSymbolAddress((void**)&attn, g_attn);

    const int ATTN_SMEM = 3 * TILE_F * (int)sizeof(float);
    cudaFuncSetAttribute(attn64, cudaFuncAttributeMaxDynamicSharedMemorySize, ATTN_SMEM);
    cudaFuncSetAttribute(mma_gemm, cudaFuncAttributeMaxDynamicSharedMemorySize, GE_SMEM_BYTES);

    const int M = BATCH * T_SEQ;    // 8192

    // 1) qkv = x @ w_qkv   (tf32 mma.sync)
    mma_gemm<<<dim3(3 * NEMB / 128, M / 128), 256, GE_SMEM_BYTES>>>(
        x, w_qkv, nullptr, qkv, M, 3 * NEMB, NEMB);

    // 2) causal flash attention (fp32)
    attn64<<<dim3(T_SEQ / 64, BATCH * NHEADS), 256, ATTN_SMEM>>>(qkv, attn);

    // 3) out = attn @ w_out + b_out   (tf32 mma.sync)
    mma_gemm<<<dim3(NEMB / 128, M / 128), 256, GE_SMEM_BYTES>>>(
        attn, w_out, b_out, out, M, NEMB, NEMB);
}

// round 7
// speedup vs baseline: 2.6685x; 1.4794x over previous
#include <cuda_runtime.h>
#include <cstdint>

#define T_SEQ 2048
#define NHEADS 16
#define NEMB 1024
#define HD 64
#define BATCH 4

// ---------------------------------------------------------------------------
// Scratch (no allocation allowed anywhere)
// ---------------------------------------------------------------------------
__device__ float g_qkv[(size_t)BATCH * T_SEQ * 3 * NEMB];   // [8192, 3072]
__device__ float g_attn[(size_t)BATCH * T_SEQ * NEMB];      // [8192, 1024]

// ---------------------------------------------------------------------------
// PTX helpers (baseline PTX only — sm_103 non-'a' target)
// ---------------------------------------------------------------------------
__device__ __forceinline__ uint32_t smem_to_u32(const void* p) {
    uint32_t a;
    asm("{ .reg .u64 t; cvta.to.shared.u64 t, %1; cvt.u32.u64 %0, t; }" : "=r"(a) : "l"(p));
    return a;
}
__device__ __forceinline__ uint32_t f2tf32(float f) {
    uint32_t u;
    asm("cvt.rna.tf32.f32 %0, %1;" : "=r"(u) : "f"(f));
    return u;
}
__device__ __forceinline__ void mma_tf32(float* d, const uint32_t* a, const uint32_t* b) {
    asm volatile(
        "mma.sync.aligned.m16n8k8.row.col.f32.tf32.tf32.f32 "
        "{%0,%1,%2,%3}, {%4,%5,%6,%7}, {%8,%9}, {%0,%1,%2,%3};"
        : "+f"(d[0]), "+f"(d[1]), "+f"(d[2]), "+f"(d[3])
        : "r"(a[0]), "r"(a[1]), "r"(a[2]), "r"(a[3]), "r"(b[0]), "r"(b[1]));
}
#define CP_ASYNC16(dst, src) \
    asm volatile("cp.async.cg.shared.global [%0], [%1], 16;" :: "r"(dst), "l"(src))
#define CP_COMMIT()  asm volatile("cp.async.commit_group;" ::: "memory")
#define CP_WAIT1()   asm volatile("cp.async.wait_group 1;" ::: "memory")
#define CP_WAIT0()   asm volatile("cp.async.wait_group 0;" ::: "memory")

// ---------------------------------------------------------------------------
// tf32 mma.sync GEMM:  C[M,N] = A[M,K] @ B[K,N]  (+bias)
// CTA 128x128, K-tile 32, 8 warps (2M x 4N), cp.async 2-stage pipeline.
// ---------------------------------------------------------------------------
#define A_STAGE 4608            // 128*36 floats
#define B_STAGE 4352            // 32*136 floats
#define GE_SMEM_BYTES (2 * (A_STAGE + B_STAGE) * 4)   // 71680

__global__ __launch_bounds__(256) void mma_gemm(const float* __restrict__ A,
                                                const float* __restrict__ B,
                                                const float* __restrict__ bias,
                                                float* __restrict__ C,
                                                int M, int N, int K) {
    extern __shared__ float sm[];
    const uint32_t sbase = smem_to_u32(sm);
    const int tid = threadIdx.x;
    const int wid = tid >> 5, lane = tid & 31;
    const int wm = wid & 1, wn = wid >> 1;
    const int lr = lane >> 2, kc = lane & 3;
    const int m0 = blockIdx.y * 128, n0 = blockIdx.x * 128;

    auto load_tile = [&](int c, int buf) {
        const uint32_t asb = sbase + (buf ? A_STAGE : 0) * 4;
        const uint32_t bsb = sbase + (2 * A_STAGE + (buf ? B_STAGE : 0)) * 4;
        const float* Ac = A + (size_t)m0 * K + c * 32;
        const float* Bc = B + (size_t)(c * 32) * N + n0;
#pragma unroll
        for (int i = 0; i < 4; i++) {
            int id = tid + i * 256;
            int am = id >> 3, ak4 = id & 7;
            CP_ASYNC16(asb + (uint32_t)(am * 36 + ak4 * 4) * 4,
                       Ac + (size_t)am * K + ak4 * 4);
            int br = id >> 5, bn4 = id & 31;
            CP_ASYNC16(bsb + (uint32_t)(br * 136 + bn4 * 4) * 4,
                       Bc + (size_t)br * N + bn4 * 4);
        }
        CP_COMMIT();
    };

    float acc[4][4][4];
#pragma unroll
    for (int i = 0; i < 4; i++)
#pragma unroll
        for (int j = 0; j < 4; j++)
#pragma unroll
            for (int r = 0; r < 4; r++) acc[i][j][r] = 0.f;

    const int NT = K >> 5;
    load_tile(0, 0);

    for (int c = 0; c < NT; c++) {
        const int buf = c & 1;
        if (c + 1 < NT) { load_tile(c + 1, buf ^ 1); CP_WAIT1(); }
        else            { CP_WAIT0(); }
        __syncthreads();

        const float* As = sm + (buf ? A_STAGE : 0);
        const float* Bs = sm + 2 * A_STAGE + (buf ? B_STAGE : 0);
        const int mbase = wm * 64, nbase = wn * 32;

#pragma unroll
        for (int kk = 0; kk < 4; kk++) {
            uint32_t af[4][4], bf[4][2];
#pragma unroll
            for (int mt = 0; mt < 4; mt++) {
                const float* ap = As + (mbase + mt * 16 + lr) * 36 + kk * 8 + kc;
                af[mt][0] = f2tf32(ap[0]);
                af[mt][1] = f2tf32(ap[8 * 36]);
                af[mt][2] = f2tf32(ap[4]);
                af[mt][3] = f2tf32(ap[8 * 36 + 4]);
            }
#pragma unroll
            for (int nt = 0; nt < 4; nt++) {
                const float* bp = Bs + (kk * 8 + kc) * 136 + nbase + nt * 8 + lr;
                bf[nt][0] = f2tf32(bp[0]);
                bf[nt][1] = f2tf32(bp[4 * 136]);
            }
#pragma unroll
            for (int mt = 0; mt < 4; mt++)
#pragma unroll
                for (int nt = 0; nt < 4; nt++)
                    mma_tf32(acc[mt][nt], af[mt], bf[nt]);
        }
        __syncthreads();
    }

#pragma unroll
    for (int mt = 0; mt < 4; mt++) {
        const int row = m0 + wm * 64 + mt * 16 + lr;
#pragma unroll
        for (int nt = 0; nt < 4; nt++) {
            const int col = n0 + wn * 32 + nt * 8 + kc * 2;
            float b0 = 0.f, b1 = 0.f;
            if (bias) { b0 = bias[col]; b1 = bias[col + 1]; }
            float2 v0 = make_float2(acc[mt][nt][0] + b0, acc[mt][nt][1] + b1);
            float2 v1 = make_float2(acc[mt][nt][2] + b0, acc[mt][nt][3] + b1);
            *(float2*)&C[(size_t)row * N + col] = v0;
            *(float2*)&C[(size_t)(row + 8) * N + col] = v1;
        }
    }
}

// ---------------------------------------------------------------------------
// Causal flash attention on tensor cores (tf32 mma.sync).
// 128 threads / 4 warps per (b, h, 64-query tile). Warp w owns query rows
// w*16..w*16+15 and the full 64-key strip.
// Smem: Qs,Ps A-layout [m][k] pitch 68 (bank = 4m+k, conflict-free);
//       Kt [d][key], Vs [key][d] B-layout [k][n] pitch 72 (bank = 8k+n).
// P roundtrip is warp-private -> __syncwarp only.
// ---------------------------------------------------------------------------
#define QP 68
#define KP 72
#define AT_QS 0
#define AT_PS (64 * QP)
#define AT_KT (2 * 64 * QP)
#define AT_VS (2 * 64 * QP + 64 * KP)
#define AT_SMEM_BYTES ((2 * 64 * QP + 2 * 64 * KP) * 4)   // 71680

__global__ __launch_bounds__(128) void attn_mma(const float* __restrict__ qkv,
                                                float* __restrict__ out) {
    extern __shared__ float sm[];
    float* Qs = sm + AT_QS;
    float* Ps = sm + AT_PS;
    float* Kt = sm + AT_KT;
    float* Vs = sm + AT_VS;

    const int tid = threadIdx.x;
    const int wid = tid >> 5, lane = tid & 31;
    const int lr = lane >> 2, kc = lane & 3;
    const int qt = blockIdx.x;
    const int b = blockIdx.y >> 4;
    const int h = blockIdx.y & 15;
    const int row0 = wid * 16 + lr;          // in-tile query rows
    const int row1 = row0 + 8;

    const float* base = qkv + (size_t)b * T_SEQ * (3 * NEMB) + h * HD;

    // Q tile -> Qs [q][d], scaled by 1/sqrt(D)
#pragma unroll
    for (int i = 0; i < 8; i++) {
        int id = tid + i * 128;
        int r = id >> 4, d4 = id & 15;
        float4 v = *(const float4*)(base + (size_t)(qt * 64 + r) * (3 * NEMB) + d4 * 4);
        v.x *= 0.125f; v.y *= 0.125f; v.z *= 0.125f; v.w *= 0.125f;
        *(float4*)&Qs[r * QP + d4 * 4] = v;
    }

    float m0 = -1e30f, m1 = -1e30f, l0 = 0.f, l1 = 0.f;
    float O[8][4];
#pragma unroll
    for (int nt = 0; nt < 8; nt++)
#pragma unroll
        for (int r = 0; r < 4; r++) O[nt][r] = 0.f;

    for (int kt = 0; kt <= qt; kt++) {
        if (kt > 0) __syncthreads();         // PV readers done before overwrite
        // K -> Kt transposed [d][key]; V -> Vs natural [key][d]
#pragma unroll
        for (int i = 0; i < 8; i++) {
            int id = tid + i * 128;
            int r = id >> 4, d4 = id & 15;
            const float* kp = base + NEMB + (size_t)(kt * 64 + r) * (3 * NEMB) + d4 * 4;
            float4 kv = *(const float4*)kp;
            float4 vv = *(const float4*)(kp + NEMB);
            Kt[(d4 * 4 + 0) * KP + r] = kv.x;
            Kt[(d4 * 4 + 1) * KP + r] = kv.y;
            Kt[(d4 * 4 + 2) * KP + r] = kv.z;
            Kt[(d4 * 4 + 3) * KP + r] = kv.w;
            *(float4*)&Vs[r * KP + d4 * 4] = vv;
        }
        __syncthreads();

        // ---- S = Q K^T : 8 k-steps x 8 n-tiles of m16n8k8
        float s[8][4];
#pragma unroll
        for (int nt = 0; nt < 8; nt++)
#pragma unroll
            for (int r = 0; r < 4; r++) s[nt][r] = 0.f;

#pragma unroll
        for (int kk = 0; kk < 8; kk++) {
            uint32_t af[4], bf[8][2];
            const float* ap = Qs + row0 * QP + kk * 8 + kc;
            af[0] = f2tf32(ap[0]);
            af[1] = f2tf32(ap[8 * QP]);
            af[2] = f2tf32(ap[4]);
            af[3] = f2tf32(ap[8 * QP + 4]);
#pragma unroll
            for (int nt = 0; nt < 8; nt++) {
                const float* bp = Kt + (kk * 8 + kc) * KP + nt * 8 + lr;
                bf[nt][0] = f2tf32(bp[0]);
                bf[nt][1] = f2tf32(bp[4 * KP]);
            }
#pragma unroll
            for (int nt = 0; nt < 8; nt++) mma_tf32(s[nt], af, bf[nt]);
        }

        if (kt == qt) {                      // causal mask (diagonal tile)
#pragma unroll
            for (int nt = 0; nt < 8; nt++) {
                int col = nt * 8 + kc * 2;
                if (col > row0)     s[nt][0] = -1e30f;
                if (col + 1 > row0) s[nt][1] = -1e30f;
                if (col > row1)     s[nt][2] = -1e30f;
                if (col + 1 > row1) s[nt][3] = -1e30f;
            }
        }

        // ---- online softmax (rows row0, row1); quad reduce over kc lanes
        float pm0 = -1e30f, pm1 = -1e30f;
#pragma unroll
        for (int nt = 0; nt < 8; nt++) {
            pm0 = fmaxf(pm0, fmaxf(s[nt][0], s[nt][1]));
            pm1 = fmaxf(pm1, fmaxf(s[nt][2], s[nt][3]));
        }
        pm0 = fmaxf(pm0, __shfl_xor_sync(0xffffffffu, pm0, 1));
        pm0 = fmaxf(pm0, __shfl_xor_sync(0xffffffffu, pm0, 2));
        pm1 = fmaxf(pm1, __shfl_xor_sync(0xffffffffu, pm1, 1));
        pm1 = fmaxf(pm1, __shfl_xor_sync(0xffffffffu, pm1, 2));

        float mn0 = fmaxf(m0, pm0), mn1 = fmaxf(m1, pm1);
        float al0 = __expf(m0 - mn0), al1 = __expf(m1 - mn1);
        m0 = mn0; m1 = mn1;

        float rs0 = 0.f, rs1 = 0.f;
#pragma unroll
        for (int nt = 0; nt < 8; nt++) {
            s[nt][0] = __expf(s[nt][0] - mn0); rs0 += s[nt][0];
            s[nt][1] = __expf(s[nt][1] - mn0); rs0 += s[nt][1];
            s[nt][2] = __expf(s[nt][2] - mn1); rs1 += s[nt][2];
            s[nt][3] = __expf(s[nt][3] - mn1); rs1 += s[nt][3];
        }
        rs0 += __shfl_xor_sync(0xffffffffu, rs0, 1);
        rs0 += __shfl_xor_sync(0xffffffffu, rs0, 2);
        rs1 += __shfl_xor_sync(0xffffffffu, rs1, 1);
        rs1 += __shfl_xor_sync(0xffffffffu, rs1, 2);
        l0 = l0 * al0 + rs0;
        l1 = l1 * al1 + rs1;

#pragma unroll
        for (int nt = 0; nt < 8; nt++) {
            O[nt][0] *= al0; O[nt][1] *= al0;
            O[nt][2] *= al1; O[nt][3] *= al1;
        }

        // ---- P -> smem (warp-private rows), then O += P V
#pragma unroll
        for (int nt = 0; nt < 8; nt++) {
            *(float2*)&Ps[row0 * QP + nt * 8 + kc * 2] = make_float2(s[nt][0], s[nt][1]);
            *(float2*)&Ps[row1 * QP + nt * 8 + kc * 2] = make_float2(s[nt][2], s[nt][3]);
        }
        __syncwarp();

#pragma unroll
        for (int kk = 0; kk < 8; kk++) {
            uint32_t af[4], bf[8][2];
            const float* ap = Ps + row0 * QP + kk * 8 + kc;
            af[0] = f2tf32(ap[0]);
            af[1] = f2tf32(ap[8 * QP]);
            af[2] = f2tf32(ap[4]);
            af[3] = f2tf32(ap[8 * QP + 4]);
#pragma unroll
            for (int nt = 0; nt < 8; nt++) {
                const float* bp = Vs + (kk * 8 + kc) * KP + nt * 8 + lr;
                bf[nt][0] = f2tf32(bp[0]);
                bf[nt][1] = f2tf32(bp[4 * KP]);
            }
#pragma unroll
            for (int nt = 0; nt < 8; nt++) mma_tf32(O[nt], af, bf[nt]);
        }
    }

    // Epilogue: normalize, write to [B*T, C] head-major
    const float inv0 = 1.0f / l0, inv1 = 1.0f / l1;
    const size_t rg0 = (size_t)b * T_SEQ + qt * 64 + row0;
#pragma unroll
    for (int nt = 0; nt < 8; nt++) {
        int col = h * HD + nt * 8 + kc * 2;
        *(float2*)&out[rg0 * NEMB + col] =
            make_float2(O[nt][0] * inv0, O[nt][1] * inv0);
        *(float2*)&out[(rg0 + 8) * NEMB + col] =
            make_float2(O[nt][2] * inv1, O[nt][3] * inv1);
    }
}

// ---------------------------------------------------------------------------
// kernel_launch
// ---------------------------------------------------------------------------
extern "C" void kernel_launch(void* const* d_in, const int* in_sizes, int n_in,
                              void* d_out, int out_size) {
    const float* x     = (const float*)d_in[0];
    const float* w_qkv = (const float*)d_in[1];
    const float* w_out = (const float*)d_in[2];
    const float* b_out = (const float*)d_in[3];
    float* out = (float*)d_out;

    float *qkv, *attn;
    cudaGetSymbolAddress((void**)&qkv, g_qkv);
    cudaGetSymbolAddress((void**)&attn, g_attn);

    cudaFuncSetAttribute(mma_gemm, cudaFuncAttributeMaxDynamicSharedMemorySize, GE_SMEM_BYTES);
    cudaFuncSetAttribute(attn_mma, cudaFuncAttributeMaxDynamicSharedMemorySize, AT_SMEM_BYTES);

    const int M = BATCH * T_SEQ;    // 8192

    mma_gemm<<<dim3(3 * NEMB / 128, M / 128), 256, GE_SMEM_BYTES>>>(
        x, w_qkv, nullptr, qkv, M, 3 * NEMB, NEMB);

    attn_mma<<<dim3(T_SEQ / 64, BATCH * NHEADS), 128, AT_SMEM_BYTES>>>(qkv, attn);

    mma_gemm<<<dim3(NEMB / 128, M / 128), 256, GE_SMEM_BYTES>>>(
        attn, w_out, b_out, out, M, NEMB, NEMB);
}

// round 8
// speedup vs baseline: 3.4855x; 1.3061x over previous
#include <cuda_runtime.h>
#include <cstdint>

#define T_SEQ 2048
#define NHEADS 16
#define NEMB 1024
#define HD 64
#define BATCH 4

// ---------------------------------------------------------------------------
// Scratch (no allocation allowed anywhere)
// ---------------------------------------------------------------------------
__device__ float g_qkv[(size_t)BATCH * T_SEQ * 3 * NEMB];   // [8192, 3072]
__device__ float g_attn[(size_t)BATCH * T_SEQ * NEMB];      // [8192, 1024]

// ---------------------------------------------------------------------------
// PTX helpers (baseline PTX only — sm_103 non-'a' target)
// ---------------------------------------------------------------------------
__device__ __forceinline__ uint32_t smem_to_u32(const void* p) {
    uint32_t a;
    asm("{ .reg .u64 t; cvta.to.shared.u64 t, %1; cvt.u32.u64 %0, t; }" : "=r"(a) : "l"(p));
    return a;
}
__device__ __forceinline__ uint32_t f2tf32(float f) {
    uint32_t u;
    asm("cvt.rna.tf32.f32 %0, %1;" : "=r"(u) : "f"(f));
    return u;
}
__device__ __forceinline__ void mma_tf32(float* d, const uint32_t* a, const uint32_t* b) {
    asm volatile(
        "mma.sync.aligned.m16n8k8.row.col.f32.tf32.tf32.f32 "
        "{%0,%1,%2,%3}, {%4,%5,%6,%7}, {%8,%9}, {%0,%1,%2,%3};"
        : "+f"(d[0]), "+f"(d[1]), "+f"(d[2]), "+f"(d[3])
        : "r"(a[0]), "r"(a[1]), "r"(a[2]), "r"(a[3]), "r"(b[0]), "r"(b[1]));
}
#define CP_ASYNC16(dst, src) \
    asm volatile("cp.async.cg.shared.global [%0], [%1], 16;" :: "r"(dst), "l"(src))
#define CP_COMMIT()  asm volatile("cp.async.commit_group;" ::: "memory")
#define CP_WAIT1()   asm volatile("cp.async.wait_group 1;" ::: "memory")
#define CP_WAIT0()   asm volatile("cp.async.wait_group 0;" ::: "memory")

// ---------------------------------------------------------------------------
// tf32 mma.sync GEMM (unchanged, measured 334us/112us):
// C[M,N] = A[M,K] @ B[K,N] (+bias). CTA 128x128, K-tile 32, 8 warps,
// cp.async 2-stage pipeline.
// ---------------------------------------------------------------------------
#define A_STAGE 4608            // 128*36 floats
#define B_STAGE 4352            // 32*136 floats
#define GE_SMEM_BYTES (2 * (A_STAGE + B_STAGE) * 4)   // 71680

__global__ __launch_bounds__(256) void mma_gemm(const float* __restrict__ A,
                                                const float* __restrict__ B,
                                                const float* __restrict__ bias,
                                                float* __restrict__ C,
                                                int M, int N, int K) {
    extern __shared__ float sm[];
    const uint32_t sbase = smem_to_u32(sm);
    const int tid = threadIdx.x;
    const int wid = tid >> 5, lane = tid & 31;
    const int wm = wid & 1, wn = wid >> 1;
    const int lr = lane >> 2, kc = lane & 3;
    const int m0 = blockIdx.y * 128, n0 = blockIdx.x * 128;

    auto load_tile = [&](int c, int buf) {
        const uint32_t asb = sbase + (buf ? A_STAGE : 0) * 4;
        const uint32_t bsb = sbase + (2 * A_STAGE + (buf ? B_STAGE : 0)) * 4;
        const float* Ac = A + (size_t)m0 * K + c * 32;
        const float* Bc = B + (size_t)(c * 32) * N + n0;
#pragma unroll
        for (int i = 0; i < 4; i++) {
            int id = tid + i * 256;
            int am = id >> 3, ak4 = id & 7;
            CP_ASYNC16(asb + (uint32_t)(am * 36 + ak4 * 4) * 4,
                       Ac + (size_t)am * K + ak4 * 4);
            int br = id >> 5, bn4 = id & 31;
            CP_ASYNC16(bsb + (uint32_t)(br * 136 + bn4 * 4) * 4,
                       Bc + (size_t)br * N + bn4 * 4);
        }
        CP_COMMIT();
    };

    float acc[4][4][4];
#pragma unroll
    for (int i = 0; i < 4; i++)
#pragma unroll
        for (int j = 0; j < 4; j++)
#pragma unroll
            for (int r = 0; r < 4; r++) acc[i][j][r] = 0.f;

    const int NT = K >> 5;
    load_tile(0, 0);

    for (int c = 0; c < NT; c++) {
        const int buf = c & 1;
        if (c + 1 < NT) { load_tile(c + 1, buf ^ 1); CP_WAIT1(); }
        else            { CP_WAIT0(); }
        __syncthreads();

        const float* As = sm + (buf ? A_STAGE : 0);
        const float* Bs = sm + 2 * A_STAGE + (buf ? B_STAGE : 0);
        const int mbase = wm * 64, nbase = wn * 32;

#pragma unroll
        for (int kk = 0; kk < 4; kk++) {
            uint32_t af[4][4], bf[4][2];
#pragma unroll
            for (int mt = 0; mt < 4; mt++) {
                const float* ap = As + (mbase + mt * 16 + lr) * 36 + kk * 8 + kc;
                af[mt][0] = f2tf32(ap[0]);
                af[mt][1] = f2tf32(ap[8 * 36]);
                af[mt][2] = f2tf32(ap[4]);
                af[mt][3] = f2tf32(ap[8 * 36 + 4]);
            }
#pragma unroll
            for (int nt = 0; nt < 4; nt++) {
                const float* bp = Bs + (kk * 8 + kc) * 136 + nbase + nt * 8 + lr;
                bf[nt][0] = f2tf32(bp[0]);
                bf[nt][1] = f2tf32(bp[4 * 136]);
            }
#pragma unroll
            for (int mt = 0; mt < 4; mt++)
#pragma unroll
                for (int nt = 0; nt < 4; nt++)
                    mma_tf32(acc[mt][nt], af[mt], bf[nt]);
        }
        __syncthreads();
    }

#pragma unroll
    for (int mt = 0; mt < 4; mt++) {
        const int row = m0 + wm * 64 + mt * 16 + lr;
#pragma unroll
        for (int nt = 0; nt < 4; nt++) {
            const int col = n0 + wn * 32 + nt * 8 + kc * 2;
            float b0 = 0.f, b1 = 0.f;
            if (bias) { b0 = bias[col]; b1 = bias[col + 1]; }
            float2 v0 = make_float2(acc[mt][nt][0] + b0, acc[mt][nt][1] + b1);
            float2 v1 = make_float2(acc[mt][nt][2] + b0, acc[mt][nt][3] + b1);
            *(float2*)&C[(size_t)row * N + col] = v0;
            *(float2*)&C[(size_t)(row + 8) * N + col] = v1;
        }
    }
}

// ---------------------------------------------------------------------------
// Causal flash attention on tensor cores (tf32 mma.sync), v2:
// 256 threads / 8 warps per (b, h, 128-query tile); warp w owns rows w*16..+15.
// K/V tiles (64 keys) cp.async double-buffered.
// K stored NATURAL [key][d] pitch 68: S B-fragment read Ks[(n)*68 + k]
//   -> bank 4*lr+kc (+8kk uniform), conflict-free, and rows are 16B-contiguous
//      for cp.async (no transpose needed).
// V natural [key][d] pitch 72: PV B-fragment bank 8*kc+lr, conflict-free.
// Qs/Ps pitch 68 A-layout, P roundtrip warp-private (__syncwarp only).
// ---------------------------------------------------------------------------
#define QP 68
#define VP 72
#define AT_QS 0
#define AT_PS  8704              // 128*68
#define AT_K0 17408              // + 64*68 = 4352 per buffer
#define AT_V0 26112              // + 64*72 = 4608 per buffer
#define AT_SMEM_BYTES (35328 * 4)   // 141312

__global__ __launch_bounds__(256) void attn_mma(const float* __restrict__ qkv,
                                                float* __restrict__ out) {
    extern __shared__ float sm[];
    const uint32_t sbase = smem_to_u32(sm);
    float* Qs = sm + AT_QS;
    float* Ps = sm + AT_PS;

    const int tid = threadIdx.x;
    const int wid = tid >> 5, lane = tid & 31;
    const int lr = lane >> 2, kc = lane & 3;
    const int qt = blockIdx.x;               // 128-row query tile, 0..15
    const int b = blockIdx.y >> 4;
    const int h = blockIdx.y & 15;
    const int row0 = wid * 16 + lr;          // in-tile query rows (0..127)
    const int row1 = row0 + 8;

    const float* base = qkv + (size_t)b * T_SEQ * (3 * NEMB) + h * HD;

    // async K/V tile loader (64 keys): K natural pitch 68, V natural pitch 72
    auto load_kv = [&](int kt, int buf) {
        const uint32_t kb = sbase + (uint32_t)(AT_K0 + buf * 4352) * 4;
        const uint32_t vb = sbase + (uint32_t)(AT_V0 + buf * 4608) * 4;
        const float* kp0 = base + NEMB + (size_t)(kt * 64) * (3 * NEMB);
#pragma unroll
        for (int i = 0; i < 4; i++) {
            int id = tid + i * 256;          // 0..1023
            int r = id >> 4, d4 = id & 15;
            const float* g = kp0 + (size_t)r * (3 * NEMB) + d4 * 4;
            CP_ASYNC16(kb + (uint32_t)(r * QP + d4 * 4) * 4, g);
            CP_ASYNC16(vb + (uint32_t)(r * VP + d4 * 4) * 4, g + NEMB);
        }
        CP_COMMIT();
    };

    load_kv(0, 0);

    // Q tile (128 rows) -> Qs, scaled by 1/sqrt(D)
#pragma unroll
    for (int i = 0; i < 8; i++) {
        int id = tid + i * 256;
        int r = id >> 4, d4 = id & 15;
        float4 v = *(const float4*)(base + (size_t)(qt * 128 + r) * (3 * NEMB) + d4 * 4);
        v.x *= 0.125f; v.y *= 0.125f; v.z *= 0.125f; v.w *= 0.125f;
        *(float4*)&Qs[r * QP + d4 * 4] = v;
    }

    float m0 = -1e30f, m1 = -1e30f, l0 = 0.f, l1 = 0.f;
    float O[8][4];
#pragma unroll
    for (int nt = 0; nt < 8; nt++)
#pragma unroll
        for (int r = 0; r < 4; r++) O[nt][r] = 0.f;

    const int NT = 2 * qt + 2;               // 64-key tiles covering causal span
    for (int kt = 0; kt < NT; kt++) {
        const int buf = kt & 1;
        __syncthreads();                     // prior compute on buf^1 done; Q visible
        if (kt + 1 < NT) { load_kv(kt + 1, buf ^ 1); CP_WAIT1(); }
        else             { CP_WAIT0(); }
        __syncthreads();                     // tile kt data visible to all warps

        const float* Ks = sm + AT_K0 + buf * 4352;
        const float* Vs = sm + AT_V0 + buf * 4608;

        // ---- S = Q K^T : 8 k-steps x 8 n-tiles of m16n8k8
        float s[8][4];
#pragma unroll
        for (int nt = 0; nt < 8; nt++)
#pragma unroll
            for (int r = 0; r < 4; r++) s[nt][r] = 0.f;

#pragma unroll
        for (int kk = 0; kk < 8; kk++) {
            uint32_t af[4], bf[8][2];
            const float* ap = Qs + row0 * QP + kk * 8 + kc;
            af[0] = f2tf32(ap[0]);
            af[1] = f2tf32(ap[8 * QP]);
            af[2] = f2tf32(ap[4]);
            af[3] = f2tf32(ap[8 * QP + 4]);
#pragma unroll
            for (int nt = 0; nt < 8; nt++) {
                const float* bp = Ks + (nt * 8 + lr) * QP + kk * 8 + kc;
                bf[nt][0] = f2tf32(bp[0]);
                bf[nt][1] = f2tf32(bp[4]);
            }
#pragma unroll
            for (int nt = 0; nt < 8; nt++) mma_tf32(s[nt], af, bf[nt]);
        }

        if (kt >= 2 * qt) {                  // diagonal-region tiles: causal mask
            const int grow0 = qt * 128 + row0;
            const int grow1 = grow0 + 8;
#pragma unroll
            for (int nt = 0; nt < 8; nt++) {
                int gc = kt * 64 + nt * 8 + kc * 2;
                if (gc > grow0)     s[nt][0] = -1e30f;
                if (gc + 1 > grow0) s[nt][1] = -1e30f;
                if (gc > grow1)     s[nt][2] = -1e30f;
                if (gc + 1 > grow1) s[nt][3] = -1e30f;
            }
        }

        // ---- online softmax (rows row0, row1); quad reduce over kc lanes
        float pm0 = -1e30f, pm1 = -1e30f;
#pragma unroll
        for (int nt = 0; nt < 8; nt++) {
            pm0 = fmaxf(pm0, fmaxf(s[nt][0], s[nt][1]));
            pm1 = fmaxf(pm1, fmaxf(s[nt][2], s[nt][3]));
        }
        pm0 = fmaxf(pm0, __shfl_xor_sync(0xffffffffu, pm0, 1));
        pm0 = fmaxf(pm0, __shfl_xor_sync(0xffffffffu, pm0, 2));
        pm1 = fmaxf(pm1, __shfl_xor_sync(0xffffffffu, pm1, 1));
        pm1 = fmaxf(pm1, __shfl_xor_sync(0xffffffffu, pm1, 2));

        float mn0 = fmaxf(m0, pm0), mn1 = fmaxf(m1, pm1);
        float al0 = __expf(m0 - mn0), al1 = __expf(m1 - mn1);
        m0 = mn0; m1 = mn1;

        float rs0 = 0.f, rs1 = 0.f;
#pragma unroll
        for (int nt = 0; nt < 8; nt++) {
            s[nt][0] = __expf(s[nt][0] - mn0); rs0 += s[nt][0];
            s[nt][1] = __expf(s[nt][1] - mn0); rs0 += s[nt][1];
            s[nt][2] = __expf(s[nt][2] - mn1); rs1 += s[nt][2];
            s[nt][3] = __expf(s[nt][3] - mn1); rs1 += s[nt][3];
        }
        rs0 += __shfl_xor_sync(0xffffffffu, rs0, 1);
        rs0 += __shfl_xor_sync(0xffffffffu, rs0, 2);
        rs1 += __shfl_xor_sync(0xffffffffu, rs1, 1);
        rs1 += __shfl_xor_sync(0xffffffffu, rs1, 2);
        l0 = l0 * al0 + rs0;
        l1 = l1 * al1 + rs1;

#pragma unroll
        for (int nt = 0; nt < 8; nt++) {
            O[nt][0] *= al0; O[nt][1] *= al0;
            O[nt][2] *= al1; O[nt][3] *= al1;
        }

        // ---- P -> smem (warp-private rows), then O += P V
#pragma unroll
        for (int nt = 0; nt < 8; nt++) {
            *(float2*)&Ps[row0 * QP + nt * 8 + kc * 2] = make_float2(s[nt][0], s[nt][1]);
            *(float2*)&Ps[row1 * QP + nt * 8 + kc * 2] = make_float2(s[nt][2], s[nt][3]);
        }
        __syncwarp();

#pragma unroll
        for (int kk = 0; kk < 8; kk++) {
            uint32_t af[4], bf[8][2];
            const float* ap = Ps + row0 * QP + kk * 8 + kc;
            af[0] = f2tf32(ap[0]);
            af[1] = f2tf32(ap[8 * QP]);
            af[2] = f2tf32(ap[4]);
            af[3] = f2tf32(ap[8 * QP + 4]);
#pragma unroll
            for (int nt = 0; nt < 8; nt++) {
                const float* bp = Vs + (kk * 8 + kc) * VP + nt * 8 + lr;
                bf[nt][0] = f2tf32(bp[0]);
                bf[nt][1] = f2tf32(bp[4 * VP]);
            }
#pragma unroll
            for (int nt = 0; nt < 8; nt++) mma_tf32(O[nt], af, bf[nt]);
        }
    }

    // Epilogue: normalize, write to [B*T, C] head-major
    const float inv0 = 1.0f / l0, inv1 = 1.0f / l1;
    const size_t rg0 = (size_t)b * T_SEQ + qt * 128 + row0;
#pragma unroll
    for (int nt = 0; nt < 8; nt++) {
        int col = h * HD + nt * 8 + kc * 2;
        *(float2*)&out[rg0 * NEMB + col] =
            make_float2(O[nt][0] * inv0, O[nt][1] * inv0);
        *(float2*)&out[(rg0 + 8) * NEMB + col] =
            make_float2(O[nt][2] * inv1, O[nt][3] * inv1);
    }
}

// ---------------------------------------------------------------------------
// kernel_launch
// ---------------------------------------------------------------------------
extern "C" void kernel_launch(void* const* d_in, const int* in_sizes, int n_in,
                              void* d_out, int out_size) {
    const float* x     = (const float*)d_in[0];
    const float* w_qkv = (const float*)d_in[1];
    const float* w_out = (const float*)d_in[2];
    const float* b_out = (const float*)d_in[3];
    float* out = (float*)d_out;

    float *qkv, *attn;
    cudaGetSymbolAddress((void**)&qkv, g_qkv);
    cudaGetSymbolAddress((void**)&attn, g_attn);

    cudaFuncSetAttribute(mma_gemm, cudaFuncAttributeMaxDynamicSharedMemorySize, GE_SMEM_BYTES);
    cudaFuncSetAttribute(attn_mma, cudaFuncAttributeMaxDynamicSharedMemorySize, AT_SMEM_BYTES);

    const int M = BATCH * T_SEQ;    // 8192

    mma_gemm<<<dim3(3 * NEMB / 128, M / 128), 256, GE_SMEM_BYTES>>>(
        x, w_qkv, nullptr, qkv, M, 3 * NEMB, NEMB);

    attn_mma<<<dim3(T_SEQ / 128, BATCH * NHEADS), 256, AT_SMEM_BYTES>>>(qkv, attn);

    mma_gemm<<<dim3(NEMB / 128, M / 128), 256, GE_SMEM_BYTES>>>(
        attn, w_out, b_out, out, M, NEMB, NEMB);
}

// round 9
// speedup vs baseline: 6.3054x; 1.8091x over previous
#include <cuda_runtime.h>
#include <cuda_fp16.h>
#include <cstdint>

#define T_SEQ 2048
#define NHEADS 16
#define NEMB 1024
#define HD 64
#define BATCH 4

// ---------------------------------------------------------------------------
// Scratch (no allocation allowed anywhere) — half-precision pipeline
// ---------------------------------------------------------------------------
__device__ __half g_xh[(size_t)BATCH * T_SEQ * NEMB];        // x in half
__device__ __half g_wqkvh[(size_t)NEMB * 3 * NEMB];          // w_qkv in half
__device__ __half g_wouth[(size_t)NEMB * NEMB];              // w_out in half
__device__ __half g_qkvh[(size_t)BATCH * T_SEQ * 3 * NEMB];  // qkv proj (half)
__device__ __half g_attnh[(size_t)BATCH * T_SEQ * NEMB];     // attn out (half)

// ---------------------------------------------------------------------------
// PTX helpers (baseline PTX only — sm_103 non-'a' target)
// ---------------------------------------------------------------------------
__device__ __forceinline__ uint32_t smem_to_u32(const void* p) {
    uint32_t a;
    asm("{ .reg .u64 t; cvta.to.shared.u64 t, %1; cvt.u32.u64 %0, t; }" : "=r"(a) : "l"(p));
    return a;
}
__device__ __forceinline__ void mma_f16(float* d, const uint32_t* a, const uint32_t* b) {
    asm volatile(
        "mma.sync.aligned.m16n8k16.row.col.f32.f16.f16.f32 "
        "{%0,%1,%2,%3}, {%4,%5,%6,%7}, {%8,%9}, {%0,%1,%2,%3};"
        : "+f"(d[0]), "+f"(d[1]), "+f"(d[2]), "+f"(d[3])
        : "r"(a[0]), "r"(a[1]), "r"(a[2]), "r"(a[3]), "r"(b[0]), "r"(b[1]));
}
#define LDSM_X4(r, addr) \
    asm volatile("ldmatrix.sync.aligned.m8n8.x4.shared.b16 {%0,%1,%2,%3}, [%4];" \
                 : "=r"((r)[0]), "=r"((r)[1]), "=r"((r)[2]), "=r"((r)[3]) : "r"(addr))
#define LDSM_X2(r, addr) \
    asm volatile("ldmatrix.sync.aligned.m8n8.x2.shared.b16 {%0,%1}, [%2];" \
                 : "=r"((r)[0]), "=r"((r)[1]) : "r"(addr))
#define LDSM_X2T(r, addr) \
    asm volatile("ldmatrix.sync.aligned.m8n8.x2.trans.shared.b16 {%0,%1}, [%2];" \
                 : "=r"((r)[0]), "=r"((r)[1]) : "r"(addr))
#define CP_ASYNC16(dst, src) \
    asm volatile("cp.async.cg.shared.global [%0], [%1], 16;" :: "r"(dst), "l"(src))
#define CP_COMMIT()  asm volatile("cp.async.commit_group;" ::: "memory")
#define CP_WAIT1()   asm volatile("cp.async.wait_group 1;" ::: "memory")
#define CP_WAIT0()   asm volatile("cp.async.wait_group 0;" ::: "memory")

// ---------------------------------------------------------------------------
// fp32 -> fp16 elementwise convert (n % 4 == 0)
// ---------------------------------------------------------------------------
__global__ void f2h(const float* __restrict__ in, __half* __restrict__ out, int n) {
    int stride = gridDim.x * blockDim.x;
    for (int i = blockIdx.x * blockDim.x + threadIdx.x; i * 4 < n; i += stride) {
        float4 v = ((const float4*)in)[i];
        __half2* o = (__half2*)(out + (size_t)i * 4);
        o[0] = __floats2half2_rn(v.x, v.y);
        o[1] = __floats2half2_rn(v.z, v.w);
    }
}

// ---------------------------------------------------------------------------
// fp16 mma.sync GEMM: C[M,N] = A[M,K] @ B[K,N], A/B half.
// half_out=1 -> C half (no bias); half_out=0 -> C float (+bias).
// CTA 128x128, K-tile 32 (2 x k16), 8 warps (2M x 4N), cp.async 2-stage.
// Smem: A [m][k] pitch 40 halves (80B rows: banks 20r mod 32, distinct);
//       B [k][n] pitch 136 halves (272B rows: banks 4k, distinct).
// Fragments via ldmatrix (A x4, B x2.trans) — zero per-element cvt.
// ---------------------------------------------------------------------------
#define HG_A0 0
#define HG_A1 10240
#define HG_B0 20480
#define HG_B1 29184
#define HG_SMEM_BYTES 37888

__global__ __launch_bounds__(256) void hgemm(const __half* __restrict__ A,
                                             const __half* __restrict__ B,
                                             const float* __restrict__ bias,
                                             void* __restrict__ Cout,
                                             int M, int N, int K, int half_out) {
    extern __shared__ char smc[];
    const uint32_t sbase = smem_to_u32(smc);
    const int tid = threadIdx.x;
    const int wid = tid >> 5, lane = tid & 31;
    const int wm = wid & 1, wn = wid >> 1;
    const int lr = lane >> 2, kc = lane & 3;
    const int m0 = blockIdx.y * 128, n0 = blockIdx.x * 128;

    auto load_tile = [&](int c, int buf) {
        const uint32_t asb = sbase + (buf ? HG_A1 : HG_A0);
        const uint32_t bsb = sbase + (buf ? HG_B1 : HG_B0);
        const __half* Ac = A + (size_t)m0 * K + c * 32;
        const __half* Bc = B + (size_t)(c * 32) * N + n0;
#pragma unroll
        for (int i = 0; i < 2; i++) {
            int id = tid + i * 256;               // 0..511
            int am = id >> 2, ak = id & 3;        // A: 128 rows x 4 chunks
            CP_ASYNC16(asb + (uint32_t)(am * 40 + ak * 8) * 2,
                       Ac + (size_t)am * K + ak * 8);
            int bk = id >> 4, bn = id & 15;       // B: 32 rows x 16 chunks
            CP_ASYNC16(bsb + (uint32_t)(bk * 136 + bn * 8) * 2,
                       Bc + (size_t)bk * N + bn * 8);
        }
        CP_COMMIT();
    };

    float acc[4][4][4];
#pragma unroll
    for (int i = 0; i < 4; i++)
#pragma unroll
        for (int j = 0; j < 4; j++)
#pragma unroll
            for (int r = 0; r < 4; r++) acc[i][j][r] = 0.f;

    const int NT = K >> 5;
    load_tile(0, 0);

    const int mbase = wm * 64, nbase = wn * 32;
    const int a_row = (lane & 15);                // ldmatrix row-in-16
    const int a_colh = (lane >> 4) * 8;           // +8 col half for matrices 2,3

    for (int c = 0; c < NT; c++) {
        const int buf = c & 1;
        if (c + 1 < NT) { load_tile(c + 1, buf ^ 1); CP_WAIT1(); }
        else            { CP_WAIT0(); }
        __syncthreads();

        const uint32_t asb = sbase + (buf ? HG_A1 : HG_A0);
        const uint32_t bsb = sbase + (buf ? HG_B1 : HG_B0);

#pragma unroll
        for (int kk = 0; kk < 2; kk++) {
            uint32_t af[4][4], bf[4][2];
            const int kb = kk * 16;
#pragma unroll
            for (int mt = 0; mt < 4; mt++) {
                uint32_t ad = asb + (uint32_t)((mbase + mt * 16 + a_row) * 40
                                               + kb + a_colh) * 2;
                LDSM_X4(af[mt], ad);
            }
#pragma unroll
            for (int nt = 0; nt < 4; nt++) {
                uint32_t bd = bsb + (uint32_t)((kb + a_row) * 136
                                               + nbase + nt * 8) * 2;
                LDSM_X2T(bf[nt], bd);
            }
#pragma unroll
            for (int mt = 0; mt < 4; mt++)
#pragma unroll
                for (int nt = 0; nt < 4; nt++)
                    mma_f16(acc[mt][nt], af[mt], bf[nt]);
        }
        __syncthreads();
    }

#pragma unroll
    for (int mt = 0; mt < 4; mt++) {
        const int row = m0 + wm * 64 + mt * 16 + lr;
#pragma unroll
        for (int nt = 0; nt < 4; nt++) {
            const int col = n0 + wn * 32 + nt * 8 + kc * 2;
            if (half_out) {
                __half* Ch = (__half*)Cout;
                *(__half2*)&Ch[(size_t)row * N + col] =
                    __floats2half2_rn(acc[mt][nt][0], acc[mt][nt][1]);
                *(__half2*)&Ch[(size_t)(row + 8) * N + col] =
                    __floats2half2_rn(acc[mt][nt][2], acc[mt][nt][3]);
            } else {
                float* Cf = (float*)Cout;
                float b0 = bias[col], b1 = bias[col + 1];
                *(float2*)&Cf[(size_t)row * N + col] =
                    make_float2(acc[mt][nt][0] + b0, acc[mt][nt][1] + b1);
                *(float2*)&Cf[(size_t)(row + 8) * N + col] =
                    make_float2(acc[mt][nt][2] + b0, acc[mt][nt][3] + b1);
            }
        }
    }
}

// ---------------------------------------------------------------------------
// Causal flash attention, fp16 mma (m16n8k16) + ldmatrix.
// 256 threads / 8 warps per (b, h, 128-query tile); warp w owns rows w*16..+15.
// Smem (halves, pitch 72 = 144B rows, banks 4r -> conflict-free, 16B aligned):
//   Qs [128][64], Ps [128][64] (A-operands, ldmatrix x4)
//   K [64][64] natural = B col-major for S (ldmatrix x2 non-trans)
//   V [64][64] natural -> B for PV via ldmatrix x2.trans
// K/V double-buffered via cp.async. Scale 1/8 applied post-MMA (exact).
// ---------------------------------------------------------------------------
#define AQ_PITCH 72
#define AT_QS_B 0
#define AT_PS_B 18432
#define AT_K_B  36864       // +9216 per buffer
#define AT_V_B  55296       // +9216 per buffer
#define ATH_SMEM_BYTES 73728

__global__ __launch_bounds__(256) void attn_h(const __half* __restrict__ qkv,
                                              __half* __restrict__ out) {
    extern __shared__ char smc[];
    const uint32_t sbase = smem_to_u32(smc);

    const int tid = threadIdx.x;
    const int wid = tid >> 5, lane = tid & 31;
    const int lr = lane >> 2, kc = lane & 3;
    const int qt = blockIdx.x;
    const int b = blockIdx.y >> 4;
    const int h = blockIdx.y & 15;
    const int row0 = wid * 16 + lr;
    const int row1 = row0 + 8;

    const __half* base = qkv + (size_t)b * T_SEQ * (3 * NEMB) + h * HD;

    auto load_kv = [&](int kt, int buf) {
        const uint32_t kb = sbase + AT_K_B + buf * 9216;
        const uint32_t vb = sbase + AT_V_B + buf * 9216;
        const __half* kp0 = base + NEMB + (size_t)(kt * 64) * (3 * NEMB);
#pragma unroll
        for (int i = 0; i < 2; i++) {
            int id = tid + i * 256;              // 0..511
            int r = id >> 3, cch = id & 7;       // 64 rows x 8 chunks
            const __half* g = kp0 + (size_t)r * (3 * NEMB) + cch * 8;
            CP_ASYNC16(kb + (uint32_t)(r * AQ_PITCH + cch * 8) * 2, g);
            CP_ASYNC16(vb + (uint32_t)(r * AQ_PITCH + cch * 8) * 2, g + NEMB);
        }
        CP_COMMIT();
    };

    load_kv(0, 0);
    // Q tile (128 rows) via cp.async (own group)
    {
        const uint32_t qb = sbase + AT_QS_B;
        const __half* qp0 = base + (size_t)(qt * 128) * (3 * NEMB);
#pragma unroll
        for (int i = 0; i < 4; i++) {
            int id = tid + i * 256;              // 0..1023
            int r = id >> 3, cch = id & 7;
            CP_ASYNC16(qb + (uint32_t)(r * AQ_PITCH + cch * 8) * 2,
                       qp0 + (size_t)r * (3 * NEMB) + cch * 8);
        }
        CP_COMMIT();
    }

    float m0 = -1e30f, m1 = -1e30f, l0 = 0.f, l1 = 0.f;
    float O[8][4];
#pragma unroll
    for (int nt = 0; nt < 8; nt++)
#pragma unroll
        for (int r = 0; r < 4; r++) O[nt][r] = 0.f;

    const int a_row = (lane & 15);
    const int a_colh = (lane >> 4) * 8;

    const int NT = 2 * qt + 2;
    for (int kt = 0; kt < NT; kt++) {
        const int buf = kt & 1;
        __syncthreads();                         // prior compute on this buf done
        if (kt + 1 < NT) { load_kv(kt + 1, buf ^ 1); CP_WAIT1(); }
        else             { CP_WAIT0(); }
        __syncthreads();                         // tile kt (and Q) visible

        const uint32_t kbuf = sbase + AT_K_B + buf * 9216;
        const uint32_t vbuf = sbase + AT_V_B + buf * 9216;
        const uint32_t qb = sbase + AT_QS_B;
        const uint32_t pb = sbase + AT_PS_B;

        // ---- S = Q K^T : 4 k16 steps x 8 n-tiles
        float s[8][4];
#pragma unroll
        for (int nt = 0; nt < 8; nt++)
#pragma unroll
            for (int r = 0; r < 4; r++) s[nt][r] = 0.f;

#pragma unroll
        for (int kk = 0; kk < 4; kk++) {
            uint32_t af[4], bf[8][2];
            LDSM_X4(af, qb + (uint32_t)((wid * 16 + a_row) * AQ_PITCH
                                        + kk * 16 + a_colh) * 2);
            const int key8 = (lane & 7), kcol = kk * 16 + ((lane >> 3) & 1) * 8;
#pragma unroll
            for (int nt = 0; nt < 8; nt++) {
                LDSM_X2(bf[nt], kbuf + (uint32_t)((nt * 8 + key8) * AQ_PITCH
                                                  + kcol) * 2);
            }
#pragma unroll
            for (int nt = 0; nt < 8; nt++) mma_f16(s[nt], af, bf[nt]);
        }

        // scale by 1/sqrt(D) = 0.125 (exact power of two)
#pragma unroll
        for (int nt = 0; nt < 8; nt++)
#pragma unroll
            for (int r = 0; r < 4; r++) s[nt][r] *= 0.125f;

        if (kt >= 2 * qt) {                      // causal mask (diagonal region)
            const int grow0 = qt * 128 + row0;
            const int grow1 = grow0 + 8;
#pragma unroll
            for (int nt = 0; nt < 8; nt++) {
                int gc = kt * 64 + nt * 8 + kc * 2;
                if (gc > grow0)     s[nt][0] = -1e30f;
                if (gc + 1 > grow0) s[nt][1] = -1e30f;
                if (gc > grow1)     s[nt][2] = -1e30f;
                if (gc + 1 > grow1) s[nt][3] = -1e30f;
            }
        }

        // ---- online softmax; quad reduce over kc lanes
        float pm0 = -1e30f, pm1 = -1e30f;
#pragma unroll
        for (int nt = 0; nt < 8; nt++) {
            pm0 = fmaxf(pm0, fmaxf(s[nt][0], s[nt][1]));
            pm1 = fmaxf(pm1, fmaxf(s[nt][2], s[nt][3]));
        }
        pm0 = fmaxf(pm0, __shfl_xor_sync(0xffffffffu, pm0, 1));
        pm0 = fmaxf(pm0, __shfl_xor_sync(0xffffffffu, pm0, 2));
        pm1 = fmaxf(pm1, __shfl_xor_sync(0xffffffffu, pm1, 1));
        pm1 = fmaxf(pm1, __shfl_xor_sync(0xffffffffu, pm1, 2));

        float mn0 = fmaxf(m0, pm0), mn1 = fmaxf(m1, pm1);
        float al0 = __expf(m0 - mn0), al1 = __expf(m1 - mn1);
        m0 = mn0; m1 = mn1;

        float rs0 = 0.f, rs1 = 0.f;
#pragma unroll
        for (int nt = 0; nt < 8; nt++) {
            s[nt][0] = __expf(s[nt][0] - mn0); rs0 += s[nt][0];
            s[nt][1] = __expf(s[nt][1] - mn0); rs0 += s[nt][1];
            s[nt][2] = __expf(s[nt][2] - mn1); rs1 += s[nt][2];
            s[nt][3] = __expf(s[nt][3] - mn1); rs1 += s[nt][3];
        }
        rs0 += __shfl_xor_sync(0xffffffffu, rs0, 1);
        rs0 += __shfl_xor_sync(0xffffffffu, rs0, 2);
        rs1 += __shfl_xor_sync(0xffffffffu, rs1, 1);
        rs1 += __shfl_xor_sync(0xffffffffu, rs1, 2);
        l0 = l0 * al0 + rs0;
        l1 = l1 * al1 + rs1;

#pragma unroll
        for (int nt = 0; nt < 8; nt++) {
            O[nt][0] *= al0; O[nt][1] *= al0;
            O[nt][2] *= al1; O[nt][3] *= al1;
        }

        // ---- P (half) -> smem, warp-private rows, then O += P V
        {
            __half* Ph = (__half*)(smc + AT_PS_B);
#pragma unroll
            for (int nt = 0; nt < 8; nt++) {
                *(__half2*)&Ph[row0 * AQ_PITCH + nt * 8 + kc * 2] =
                    __floats2half2_rn(s[nt][0], s[nt][1]);
                *(__half2*)&Ph[row1 * AQ_PITCH + nt * 8 + kc * 2] =
                    __floats2half2_rn(s[nt][2], s[nt][3]);
            }
        }
        __syncwarp();

#pragma unroll
        for (int kk = 0; kk < 4; kk++) {
            uint32_t af[4], bf[8][2];
            LDSM_X4(af, pb + (uint32_t)((wid * 16 + a_row) * AQ_PITCH
                                        + kk * 16 + a_colh) * 2);
            const int keyr = kk * 16 + (lane & 15);
#pragma unroll
            for (int nt = 0; nt < 8; nt++) {
                LDSM_X2T(bf[nt], vbuf + (uint32_t)(keyr * AQ_PITCH + nt * 8) * 2);
            }
#pragma unroll
            for (int nt = 0; nt < 8; nt++) mma_f16(O[nt], af, bf[nt]);
        }
    }

    // Epilogue: normalize, convert to half, write [B*T, C] head-major
    const float inv0 = 1.0f / l0, inv1 = 1.0f / l1;
    const size_t rg0 = (size_t)b * T_SEQ + qt * 128 + row0;
#pragma unroll
    for (int nt = 0; nt < 8; nt++) {
        int col = h * HD + nt * 8 + kc * 2;
        *(__half2*)&out[rg0 * NEMB + col] =
            __floats2half2_rn(O[nt][0] * inv0, O[nt][1] * inv0);
        *(__half2*)&out[(rg0 + 8) * NEMB + col] =
            __floats2half2_rn(O[nt][2] * inv1, O[nt][3] * inv1);
    }
}

// ---------------------------------------------------------------------------
// kernel_launch: convert -> qkv hgemm -> attention -> out hgemm(+bias, fp32)
// ---------------------------------------------------------------------------
extern "C" void kernel_launch(void* const* d_in, const int* in_sizes, int n_in,
                              void* d_out, int out_size) {
    const float* x     = (const float*)d_in[0];
    const float* w_qkv = (const float*)d_in[1];
    const float* w_out = (const float*)d_in[2];
    const float* b_out = (const float*)d_in[3];
    float* out = (float*)d_out;

    __half *xh, *wqkvh, *wouth, *qkvh, *attnh;
    cudaGetSymbolAddress((void**)&xh, g_xh);
    cudaGetSymbolAddress((void**)&wqkvh, g_wqkvh);
    cudaGetSymbolAddress((void**)&wouth, g_wouth);
    cudaGetSymbolAddress((void**)&qkvh, g_qkvh);
    cudaGetSymbolAddress((void**)&attnh, g_attnh);

    cudaFuncSetAttribute(hgemm, cudaFuncAttributeMaxDynamicSharedMemorySize, HG_SMEM_BYTES);
    cudaFuncSetAttribute(attn_h, cudaFuncAttributeMaxDynamicSharedMemorySize, ATH_SMEM_BYTES);

    const int M = BATCH * T_SEQ;    // 8192

    // 0) fp32 -> fp16 converts
    f2h<<<512, 256>>>(x, xh, M * NEMB);
    f2h<<<512, 256>>>(w_qkv, wqkvh, NEMB * 3 * NEMB);
    f2h<<<256, 256>>>(w_out, wouth, NEMB * NEMB);

    // 1) qkv = x @ w_qkv  (fp16 tensor cores, half output)
    hgemm<<<dim3(3 * NEMB / 128, M / 128), 256, HG_SMEM_BYTES>>>(
        xh, wqkvh, nullptr, qkvh, M, 3 * NEMB, NEMB, 1);

    // 2) causal flash attention (fp16 mma, half output)
    attn_h<<<dim3(T_SEQ / 128, BATCH * NHEADS), 256, ATH_SMEM_BYTES>>>(qkvh, attnh);

    // 3) out = attn @ w_out + b_out  (fp16 tensor cores, fp32 output)
    hgemm<<<dim3(NEMB / 128, M / 128), 256, HG_SMEM_BYTES>>>(
        attnh, wouth, b_out, out, M, NEMB, NEMB, 0);
}